// round 5
// baseline (speedup 1.0000x reference)
#include <cuda_runtime.h>
#include <cuda.h>
#include <cstdint>

typedef unsigned long long ull;
#define FULLMASK 0xffffffffu

__device__ float g_pooled[20000 * 10];

__device__ __forceinline__ ull pk2(float x, float y) {
    ull r; asm("mov.b64 %0, {%1, %2};" : "=l"(r) : "f"(x), "f"(y)); return r;
}
__device__ __forceinline__ float2 upk2(ull p) {
    float2 t; asm("mov.b64 {%0, %1}, %2;" : "=f"(t.x), "=f"(t.y) : "l"(p)); return t;
}
__device__ __forceinline__ void fma2(ull& d, ull a, ull b) {
    asm("fma.rn.f32x2 %0, %1, %2, %0;" : "+l"(d) : "l"(a), "l"(b));
}
__device__ __forceinline__ void add2(ull& d, ull a) {
    asm("add.rn.f32x2 %0, %0, %1;" : "+l"(d) : "l"(a));
}
#define BAR(id, n) asm volatile("bar.sync %0, %1;" :: "r"(id), "r"(n) : "memory")

// ---- smem layout (bytes) ----
#define BUFB   32768
#define W1OFF  (4 * BUFB)            // 131072
#define SCROFF (W1OFF + 10240)       // 141312 (scratch 30720 B)
#define MBOFF  (SCROFF + 30720)      // 172032
#define K2AOFF (MBOFF + 64)          // 172096 : [2][16][68] f
#define K2BOFF (K2AOFF + 8704)       // 180800 : [2][16][132] f
#define SMEMT  (K2BOFF + 16896)      // 197696

__device__ __forceinline__ void mbar_wait(uint32_t mb, uint32_t ph) {
    uint32_t done;
    asm volatile("{\n\t.reg .pred p;\n\t"
        "mbarrier.try_wait.parity.acquire.cta.shared::cta.b64 p, [%1], %2;\n\t"
        "selp.b32 %0, 1, 0, p;\n\t}" : "=r"(done) : "r"(mb), "r"(ph) : "memory");
    while (!done) {
        asm volatile("{\n\t.reg .pred p;\n\t"
            "mbarrier.try_wait.parity.acquire.cta.shared::cta.b64 p, [%1], %2, 10000000;\n\t"
            "selp.b32 %0, 1, 0, p;\n\t}" : "=r"(done) : "r"(mb), "r"(ph) : "memory");
    }
}

// ---------------------------------------------------------------------------
// Fused: warps 0-7 = neighbor MLP+maxpool (TMA), warps 8-11 = self@Wt2 GEMM.
// ---------------------------------------------------------------------------
__global__ void __launch_bounds__(384, 1)
fused_k1k2(const __grid_constant__ CUtensorMap tmap,
           const float* __restrict__ W1,
           const float* __restrict__ A, const float* __restrict__ Bw,
           const float* __restrict__ bt2, float* __restrict__ out, int B)
{
    extern __shared__ char sm[];
    const uint32_t smb = (uint32_t)__cvta_generic_to_shared(sm);
    const int t = threadIdx.x;
    const int G = gridDim.x, bid = blockIdx.x;

    if (t < 256) {
        // ================= k1 role =================
        float* w1s = (float*)(sm + W1OFF);
        ull* scr = (ull*)(sm + SCROFF);
        const uint32_t mb0 = smb + MBOFF;
        const int lane = t & 31, warp = t >> 5;
        const int ds = t >> 6, rbase = t & 63;

        for (int i = t; i < 2560; i += 256) w1s[i] = W1[i];
        if (t == 0) {
            #pragma unroll
            for (int s = 0; s < 4; s++)
                asm volatile("mbarrier.init.shared.b64 [%0], 1;" :: "r"(mb0 + 8 * s) : "memory");
            asm volatile("fence.proxy.async.shared::cta;" ::: "memory");
        }
        BAR(1, 256);

        const int NT = (B * 32 + 255) >> 8;
        const int ntiles = (bid < NT) ? (NT - bid + G - 1) / G : 0;
        const int totc = ntiles * 8;

        auto issue = [&](int i) {
            int gt = bid + G * (i >> 3);
            uint32_t dst = smb + (i & 3) * BUFB;
            uint32_t mb = mb0 + 8 * (i & 3);
            asm volatile("mbarrier.arrive.expect_tx.shared.b64 _, [%0], %1;"
                         :: "r"(mb), "r"(32768u) : "memory");
            int x = (i & 7) * 32, y = gt * 256;
            asm volatile("cp.async.bulk.tensor.2d.shared::cta.global.tile.mbarrier::complete_tx::bytes"
                         " [%0], [%1, {%2, %3}], [%4];"
                         :: "r"(dst), "l"(&tmap), "r"(x), "r"(y), "r"(mb) : "memory");
        };
        if (t == 0) { int pre = totc < 3 ? totc : 3; for (int i = 0; i < pre; i++) issue(i); }

        ull acc[4][5];
        #pragma unroll
        for (int q = 0; q < 4; q++)
            #pragma unroll
            for (int jp = 0; jp < 5; jp++) acc[q][jp] = 0ull;

        #pragma unroll 1
        for (int i = 0; i < totc; i++) {
            if (t == 0 && i + 3 < totc) issue(i + 3);
            mbar_wait(mb0 + 8 * (i & 3), (uint32_t)((i >> 2) & 1));

            const char* bb = sm + (i & 3) * BUFB;
            const int c = i & 7;
            #pragma unroll
            for (int g = 0; g < 2; g++) {
                const int dg = c * 32 + ds * 8 + g * 4;
                ull wpk[4][5];
                #pragma unroll
                for (int dd = 0; dd < 4; dd++)
                    #pragma unroll
                    for (int jp = 0; jp < 5; jp++)
                        wpk[dd][jp] = *(const ull*)&w1s[(dg + dd) * 10 + 2 * jp];
                #pragma unroll
                for (int q = 0; q < 4; q++) {
                    int r = rbase + 64 * q;
                    int off = r * 128 + (2 * ds + g) * 16;
                    int phys = off ^ ((r & 7) << 4);
                    float4 x = *(const float4*)(bb + phys);
                    ull p0 = pk2(x.x, x.x), p1 = pk2(x.y, x.y);
                    ull p2 = pk2(x.z, x.z), p3 = pk2(x.w, x.w);
                    #pragma unroll
                    for (int jp = 0; jp < 5; jp++) {
                        fma2(acc[q][jp], p0, wpk[0][jp]);
                        fma2(acc[q][jp], p1, wpk[1][jp]);
                        fma2(acc[q][jp], p2, wpk[2][jp]);
                        fma2(acc[q][jp], p3, wpk[3][jp]);
                    }
                }
            }

            if (c == 7) {
                const int gt = bid + G * (i >> 3);
                if (ds) {
                    ull* dp = scr + (((ds - 1) * 64 + rbase) * 4) * 5;
                    #pragma unroll
                    for (int q = 0; q < 4; q++)
                        #pragma unroll
                        for (int jp = 0; jp < 5; jp++) dp[q * 5 + jp] = acc[q][jp];
                }
                BAR(1, 256);
                if (ds == 0) {
                    #pragma unroll
                    for (int s = 0; s < 3; s++) {
                        const ull* sp = scr + ((s * 64 + rbase) * 4) * 5;
                        #pragma unroll
                        for (int q = 0; q < 4; q++)
                            #pragma unroll
                            for (int jp = 0; jp < 5; jp++) add2(acc[q][jp], sp[q * 5 + jp]);
                    }
                    #pragma unroll
                    for (int q = 0; q < 4; q++) {
                        float h[10];
                        #pragma unroll
                        for (int jp = 0; jp < 5; jp++) {
                            float2 v = upk2(acc[q][jp]);
                            h[2 * jp] = v.x; h[2 * jp + 1] = v.y;
                        }
                        #pragma unroll
                        for (int j = 0; j < 10; j++)
                            #pragma unroll
                            for (int o = 16; o > 0; o >>= 1)
                                h[j] = fmaxf(h[j], __shfl_xor_sync(FULLMASK, h[j], o));
                        if (lane == 0) {
                            int b = gt * 8 + 2 * q + warp;
                            if (b < B) {
                                #pragma unroll
                                for (int j = 0; j < 10; j++)
                                    g_pooled[(size_t)b * 10 + j] = h[j];
                            }
                        }
                    }
                }
                #pragma unroll
                for (int q = 0; q < 4; q++)
                    #pragma unroll
                    for (int jp = 0; jp < 5; jp++) acc[q][jp] = 0ull;
            }
            BAR(1, 256);
        }
    } else {
        // ================= k2 role: 128 threads, 64x128 tiles =================
        const int wt = t - 256;
        float* As = (float*)(sm + K2AOFF);   // [2][16][68]
        float* Bs = (float*)(sm + K2BOFF);   // [2][16][132]
        const int tx = wt & 15, ty = wt >> 4;
        const int M = B;
        const int jobs = ((M + 63) >> 6) * 4;

        auto loadAB = [&](int m0, int n0, int k0, int buf) {
            float* as = As + buf * 1088;
            float* bs = Bs + buf * 2112;
            #pragma unroll
            for (int i = 0; i < 2; i++) {
                int idx = wt + 128 * i;
                int m = idx >> 2, kq = (idx & 3) << 2;
                float4 va = make_float4(0.f, 0.f, 0.f, 0.f);
                if (m0 + m < M) va = *(const float4*)(A + (size_t)(m0 + m) * 256 + k0 + kq);
                as[(kq + 0) * 68 + m] = va.x; as[(kq + 1) * 68 + m] = va.y;
                as[(kq + 2) * 68 + m] = va.z; as[(kq + 3) * 68 + m] = va.w;
            }
            #pragma unroll
            for (int i = 0; i < 4; i++) {
                int idx = wt + 128 * i;
                int kb = idx >> 5, nq = (idx & 31) << 2;
                *(float4*)&bs[kb * 132 + nq] = *(const float4*)(Bw + (size_t)(k0 + kb) * 512 + n0 + nq);
            }
        };

        for (int j = bid; j < jobs; j += G) {
            const int m0 = (j >> 2) * 64, n0 = (j & 3) * 128;
            ull acc[4][8];
            #pragma unroll
            for (int p = 0; p < 4; p++)
                #pragma unroll
                for (int n = 0; n < 8; n++) acc[p][n] = 0ull;

            loadAB(m0, n0, 0, 0);
            BAR(2, 128);
            #pragma unroll 1
            for (int s = 0; s < 16; s++) {
                if (s + 1 < 16) loadAB(m0, n0, (s + 1) * 16, (s + 1) & 1);
                const float* as = As + (s & 1) * 1088;
                const float* bs = Bs + (s & 1) * 2112;
                #pragma unroll
                for (int kk = 0; kk < 16; kk++) {
                    ull a[4];
                    #pragma unroll
                    for (int p = 0; p < 4; p++)
                        a[p] = *(const ull*)&as[kk * 68 + ty * 8 + 2 * p];
                    float4 b0 = *(const float4*)&bs[kk * 132 + tx * 8];
                    float4 b1 = *(const float4*)&bs[kk * 132 + tx * 8 + 4];
                    ull pb[8] = {pk2(b0.x, b0.x), pk2(b0.y, b0.y), pk2(b0.z, b0.z), pk2(b0.w, b0.w),
                                 pk2(b1.x, b1.x), pk2(b1.y, b1.y), pk2(b1.z, b1.z), pk2(b1.w, b1.w)};
                    #pragma unroll
                    for (int p = 0; p < 4; p++)
                        #pragma unroll
                        for (int n = 0; n < 8; n++)
                            fma2(acc[p][n], a[p], pb[n]);
                }
                BAR(2, 128);
            }

            float bv[8];
            #pragma unroll
            for (int n = 0; n < 8; n++) bv[n] = bt2[n0 + tx * 8 + n];
            #pragma unroll
            for (int p = 0; p < 4; p++) {
                float2 c[8];
                #pragma unroll
                for (int n = 0; n < 8; n++) c[n] = upk2(acc[p][n]);
                int r0 = m0 + ty * 8 + 2 * p;
                #pragma unroll
                for (int h = 0; h < 2; h++) {
                    int row = r0 + h;
                    if (row < M) {
                        float4 o0 = make_float4((h ? c[0].y : c[0].x) + bv[0], (h ? c[1].y : c[1].x) + bv[1],
                                                (h ? c[2].y : c[2].x) + bv[2], (h ? c[3].y : c[3].x) + bv[3]);
                        float4 o1 = make_float4((h ? c[4].y : c[4].x) + bv[4], (h ? c[5].y : c[5].x) + bv[5],
                                                (h ? c[6].y : c[6].x) + bv[6], (h ? c[7].y : c[7].x) + bv[7]);
                        *(float4*)(out + (size_t)row * 1024 + n0 + tx * 8) = o0;
                        *(float4*)(out + (size_t)row * 1024 + n0 + tx * 8 + 4) = o1;
                    }
                }
            }
        }
    }
}

// ---------------------------------------------------------------------------
__global__ void __launch_bounds__(512)
k3_neigh_out(const float* __restrict__ b1, const float* __restrict__ Wt1,
             const float* __restrict__ bt1, float* __restrict__ out, int B)
{
    __shared__ float ps[1280];
    const int o = threadIdx.x;
    const int b0 = blockIdx.x * 128;
    const int nrows = min(128, B - b0);

    for (int idx = o; idx < nrows * 10; idx += 512) {
        int j = idx % 10;
        ps[idx] = fmaxf(g_pooled[(size_t)b0 * 10 + idx] + b1[j], 0.0f);
    }
    ull wtp[5];
    #pragma unroll
    for (int jp = 0; jp < 5; jp++)
        wtp[jp] = pk2(Wt1[(2 * jp) * 512 + o], Wt1[(2 * jp + 1) * 512 + o]);
    float bias = bt1[o];
    __syncthreads();

    for (int r = 0; r < nrows; r++) {
        const ull* pr = (const ull*)&ps[r * 10];
        ull s2 = 0ull;
        #pragma unroll
        for (int jp = 0; jp < 5; jp++) fma2(s2, pr[jp], wtp[jp]);
        float2 t = upk2(s2);
        out[(size_t)(b0 + r) * 1024 + 512 + o] = t.x + t.y + bias;
    }
}

// ---------------------------------------------------------------------------
typedef CUresult (*EncodeFn)(CUtensorMap*, CUtensorMapDataType, cuuint32_t, void*,
                             const cuuint64_t*, const cuuint64_t*, const cuuint32_t*,
                             const cuuint32_t*, CUtensorMapInterleave, CUtensorMapSwizzle,
                             CUtensorMapL2promotion, CUtensorMapFloatOOBfill);

extern "C" void kernel_launch(void* const* d_in, const int* in_sizes, int n_in,
                              void* d_out, int out_size)
{
    const float* self_vecs = (const float*)d_in[0];
    const float* neigh     = (const float*)d_in[1];
    const float* W1        = (const float*)d_in[2];
    const float* b1        = (const float*)d_in[3];
    const float* Wt1       = (const float*)d_in[4];
    const float* bt1       = (const float*)d_in[5];
    const float* Wt2       = (const float*)d_in[6];
    const float* bt2       = (const float*)d_in[7];
    float* out = (float*)d_out;

    const int B = in_sizes[0] / 256;

    CUtensorMap tmap;
    EncodeFn enc = nullptr;
    cudaDriverEntryPointQueryResult qr;
    cudaGetDriverEntryPointByVersion("cuTensorMapEncodeTiled", (void**)&enc, 12000,
                                     cudaEnableDefault, &qr);
    cuuint64_t gdim[2] = {256ull, (cuuint64_t)B * 32ull};
    cuuint64_t gstr[1] = {256ull * 4ull};
    cuuint32_t box[2]  = {32u, 256u};
    cuuint32_t est[2]  = {1u, 1u};
    enc(&tmap, CU_TENSOR_MAP_DATA_TYPE_FLOAT32, 2, (void*)neigh, gdim, gstr, box, est,
        CU_TENSOR_MAP_INTERLEAVE_NONE, CU_TENSOR_MAP_SWIZZLE_128B,
        CU_TENSOR_MAP_L2_PROMOTION_L2_128B, CU_TENSOR_MAP_FLOAT_OOB_FILL_NONE);

    cudaFuncSetAttribute(fused_k1k2, cudaFuncAttributeMaxDynamicSharedMemorySize, SMEMT);
    fused_k1k2<<<148, 384, SMEMT>>>(tmap, W1, self_vecs, Wt2, bt2, out, B);

    k3_neigh_out<<<(B + 127) / 128, 512>>>(b1, Wt1, bt1, out, B);
}

// round 7
// speedup vs baseline: 1.3229x; 1.3229x over previous
#include <cuda_runtime.h>
#include <cuda.h>
#include <cstdint>

typedef unsigned long long ull;
#define FULLMASK 0xffffffffu

__device__ float g_pooled[20000 * 10];

__device__ __forceinline__ ull pk2(float x, float y) {
    ull r; asm("mov.b64 %0, {%1, %2};" : "=l"(r) : "f"(x), "f"(y)); return r;
}
__device__ __forceinline__ float2 upk2(ull p) {
    float2 t; asm("mov.b64 {%0, %1}, %2;" : "=f"(t.x), "=f"(t.y) : "l"(p)); return t;
}
__device__ __forceinline__ void fma2(ull& d, ull a, ull b) {
    asm("fma.rn.f32x2 %0, %1, %2, %0;" : "+l"(d) : "l"(a), "l"(b));
}
__device__ __forceinline__ void add2(ull& d, ull a) {
    asm("add.rn.f32x2 %0, %0, %1;" : "+l"(d) : "l"(a));
}
__device__ __forceinline__ float tf32r(float x) {
    uint32_t o; asm("cvt.rna.tf32.f32 %0, %1;" : "=r"(o) : "f"(x));
    return __uint_as_float(o);
}
__device__ __forceinline__ void mbar_wait(uint32_t mb, uint32_t ph) {
    uint32_t done;
    asm volatile("{\n\t.reg .pred p;\n\t"
        "mbarrier.try_wait.parity.acquire.cta.shared::cta.b64 p, [%1], %2;\n\t"
        "selp.b32 %0, 1, 0, p;\n\t}" : "=r"(done) : "r"(mb), "r"(ph) : "memory");
    while (!done) {
        asm volatile("{\n\t.reg .pred p;\n\t"
            "mbarrier.try_wait.parity.acquire.cta.shared::cta.b64 p, [%1], %2, 10000000;\n\t"
            "selp.b32 %0, 1, 0, p;\n\t}" : "=r"(done) : "r"(mb), "r"(ph) : "memory");
    }
}

// =================== k1 (unchanged, proven: TMA MLP+maxpool, 121 us) ===================
#define BUFB   32768
#define W1OFF  (4 * BUFB)
#define SCROFF (W1OFF + 10240)
#define MBOFF  (SCROFF + 30720)
#define K1SMEM (MBOFF + 64)

__global__ void __launch_bounds__(256, 1)
k1_neigh_pool(const __grid_constant__ CUtensorMap tmap,
              const float* __restrict__ W1, int B)
{
    extern __shared__ char sm[];
    float* w1s = (float*)(sm + W1OFF);
    ull* scr = (ull*)(sm + SCROFF);
    const uint32_t smb = (uint32_t)__cvta_generic_to_shared(sm);
    const uint32_t mb0 = smb + MBOFF;
    const int t = threadIdx.x;
    const int lane = t & 31, warp = t >> 5;
    const int ds = t >> 6, rbase = t & 63;
    const int G = gridDim.x, bid = blockIdx.x;

    for (int i = t; i < 2560; i += 256) w1s[i] = W1[i];
    if (t == 0) {
        #pragma unroll
        for (int s = 0; s < 4; s++)
            asm volatile("mbarrier.init.shared.b64 [%0], 1;" :: "r"(mb0 + 8 * s) : "memory");
        asm volatile("fence.proxy.async.shared::cta;" ::: "memory");
    }
    __syncthreads();

    const int NT = (B * 32 + 255) >> 8;
    const int ntiles = (bid < NT) ? (NT - bid + G - 1) / G : 0;
    const int totc = ntiles * 8;

    auto issue = [&](int i) {
        int gt = bid + G * (i >> 3);
        uint32_t dst = smb + (i & 3) * BUFB;
        uint32_t mb = mb0 + 8 * (i & 3);
        asm volatile("mbarrier.arrive.expect_tx.shared.b64 _, [%0], %1;"
                     :: "r"(mb), "r"(32768u) : "memory");
        int x = (i & 7) * 32, y = gt * 256;
        asm volatile("cp.async.bulk.tensor.2d.shared::cta.global.tile.mbarrier::complete_tx::bytes"
                     " [%0], [%1, {%2, %3}], [%4];"
                     :: "r"(dst), "l"(&tmap), "r"(x), "r"(y), "r"(mb) : "memory");
    };
    if (t == 0) { int pre = totc < 3 ? totc : 3; for (int i = 0; i < pre; i++) issue(i); }

    ull acc[4][5];
    #pragma unroll
    for (int q = 0; q < 4; q++)
        #pragma unroll
        for (int jp = 0; jp < 5; jp++) acc[q][jp] = 0ull;

    #pragma unroll 1
    for (int i = 0; i < totc; i++) {
        if (t == 0 && i + 3 < totc) issue(i + 3);
        mbar_wait(mb0 + 8 * (i & 3), (uint32_t)((i >> 2) & 1));

        const char* bb = sm + (i & 3) * BUFB;
        const int c = i & 7;
        #pragma unroll
        for (int g = 0; g < 2; g++) {
            const int dg = c * 32 + ds * 8 + g * 4;
            ull wpk[4][5];
            #pragma unroll
            for (int dd = 0; dd < 4; dd++)
                #pragma unroll
                for (int jp = 0; jp < 5; jp++)
                    wpk[dd][jp] = *(const ull*)&w1s[(dg + dd) * 10 + 2 * jp];
            #pragma unroll
            for (int q = 0; q < 4; q++) {
                int r = rbase + 64 * q;
                int off = r * 128 + (2 * ds + g) * 16;
                int phys = off ^ ((r & 7) << 4);
                float4 x = *(const float4*)(bb + phys);
                ull p0 = pk2(x.x, x.x), p1 = pk2(x.y, x.y);
                ull p2 = pk2(x.z, x.z), p3 = pk2(x.w, x.w);
                #pragma unroll
                for (int jp = 0; jp < 5; jp++) {
                    fma2(acc[q][jp], p0, wpk[0][jp]);
                    fma2(acc[q][jp], p1, wpk[1][jp]);
                    fma2(acc[q][jp], p2, wpk[2][jp]);
                    fma2(acc[q][jp], p3, wpk[3][jp]);
                }
            }
        }

        if (c == 7) {
            const int gt = bid + G * (i >> 3);
            if (ds) {
                ull* dp = scr + (((ds - 1) * 64 + rbase) * 4) * 5;
                #pragma unroll
                for (int q = 0; q < 4; q++)
                    #pragma unroll
                    for (int jp = 0; jp < 5; jp++) dp[q * 5 + jp] = acc[q][jp];
            }
            __syncthreads();
            if (ds == 0) {
                #pragma unroll
                for (int s = 0; s < 3; s++) {
                    const ull* sp = scr + ((s * 64 + rbase) * 4) * 5;
                    #pragma unroll
                    for (int q = 0; q < 4; q++)
                        #pragma unroll
                        for (int jp = 0; jp < 5; jp++) add2(acc[q][jp], sp[q * 5 + jp]);
                }
                #pragma unroll
                for (int q = 0; q < 4; q++) {
                    float h[10];
                    #pragma unroll
                    for (int jp = 0; jp < 5; jp++) {
                        float2 v = upk2(acc[q][jp]);
                        h[2 * jp] = v.x; h[2 * jp + 1] = v.y;
                    }
                    #pragma unroll
                    for (int j = 0; j < 10; j++)
                        #pragma unroll
                        for (int o = 16; o > 0; o >>= 1)
                            h[j] = fmaxf(h[j], __shfl_xor_sync(FULLMASK, h[j], o));
                    if (lane == 0) {
                        int b = gt * 8 + 2 * q + warp;
                        if (b < B) {
                            #pragma unroll
                            for (int j = 0; j < 10; j++)
                                g_pooled[(size_t)b * 10 + j] = h[j];
                        }
                    }
                }
            }
            #pragma unroll
            for (int q = 0; q < 4; q++)
                #pragma unroll
                for (int jp = 0; jp < 5; jp++) acc[q][jp] = 0ull;
        }
        __syncthreads();
    }
}

// =================== k2: mma.sync tf32 GEMM, self @ Wt2 + bt2 ===================
// Block 512 thr (16 warps), tile 128(M) x 256(N), BK=32, double-buffered smem.
// Warp wm=wid>>1 owns m16 slice, wn=wid&1 owns 128-col half (16 n8 tiles).
#define APAD 36
#define BPAD 264
#define ABUF (128 * APAD)          // floats
#define BBUF (32 * BPAD)           // floats
#define K2SMEM ((2 * ABUF + 2 * BBUF) * 4)   // 104448 B

__device__ __forceinline__ void mma8(float* c, uint32_t a0, uint32_t a1, uint32_t a2,
                                     uint32_t a3, uint32_t b0, uint32_t b1) {
    asm volatile("mma.sync.aligned.m16n8k8.row.col.f32.tf32.tf32.f32 "
                 "{%0,%1,%2,%3}, {%4,%5,%6,%7}, {%8,%9}, {%0,%1,%2,%3};"
                 : "+f"(c[0]), "+f"(c[1]), "+f"(c[2]), "+f"(c[3])
                 : "r"(a0), "r"(a1), "r"(a2), "r"(a3), "r"(b0), "r"(b1));
}

__global__ void __launch_bounds__(512, 1)
k2_mma(const float* __restrict__ A, const float* __restrict__ Bw,
       const float* __restrict__ bias, float* __restrict__ out, int M)
{
    extern __shared__ float sms[];
    float* As = sms;                  // [2][128][APAD]
    float* Bs = sms + 2 * ABUF;       // [2][32][BPAD]
    const int t = threadIdx.x;
    const int wid = t >> 5, lane = t & 31;
    const int wm = wid >> 1, wn = wid & 1;
    const int m0 = (blockIdx.x >> 1) * 128;
    const int n0 = (blockIdx.x & 1) * 256;

    auto load = [&](int kc, int buf) {
        float* as = As + buf * ABUF;
        float* bs = Bs + buf * BBUF;
        const int k0 = kc * 32;
        #pragma unroll
        for (int i = 0; i < 2; i++) {
            int idx = t + 512 * i;
            int row = idx >> 3, kq = (idx & 7) << 2;
            float4 v = make_float4(0.f, 0.f, 0.f, 0.f);
            if (m0 + row < M) v = *(const float4*)(A + (size_t)(m0 + row) * 256 + k0 + kq);
            float* d = &as[row * APAD + kq];
            d[0] = tf32r(v.x); d[1] = tf32r(v.y); d[2] = tf32r(v.z); d[3] = tf32r(v.w);
        }
        #pragma unroll
        for (int i = 0; i < 4; i++) {
            int idx = t + 512 * i;
            int k = idx >> 6, nq = (idx & 63) << 2;
            float4 v = *(const float4*)(Bw + (size_t)(k0 + k) * 512 + n0 + nq);
            float* d = &bs[k * BPAD + nq];
            d[0] = tf32r(v.x); d[1] = tf32r(v.y); d[2] = tf32r(v.z); d[3] = tf32r(v.w);
        }
    };

    float acc[16][4];
    #pragma unroll
    for (int nt = 0; nt < 16; nt++)
        #pragma unroll
        for (int j = 0; j < 4; j++) acc[nt][j] = 0.f;

    load(0, 0);
    __syncthreads();

    #pragma unroll 1
    for (int kc = 0; kc < 8; kc++) {
        if (kc + 1 < 8) load(kc + 1, (kc + 1) & 1);
        const float* as = As + (kc & 1) * ABUF;
        const float* bs = Bs + (kc & 1) * BBUF;
        const int r0 = wm * 16 + (lane >> 2);
        #pragma unroll
        for (int s = 0; s < 4; s++) {
            const int c0 = s * 8 + (lane & 3);
            uint32_t a0 = __float_as_uint(as[r0 * APAD + c0]);
            uint32_t a1 = __float_as_uint(as[(r0 + 8) * APAD + c0]);
            uint32_t a2 = __float_as_uint(as[r0 * APAD + c0 + 4]);
            uint32_t a3 = __float_as_uint(as[(r0 + 8) * APAD + c0 + 4]);
            const int kb0 = (s * 8 + (lane & 3)) * BPAD;
            const int kb1 = kb0 + 4 * BPAD;
            const int nb = wn * 128 + (lane >> 2);
            #pragma unroll
            for (int nt = 0; nt < 16; nt++) {
                uint32_t b0 = __float_as_uint(bs[kb0 + nb + nt * 8]);
                uint32_t b1 = __float_as_uint(bs[kb1 + nb + nt * 8]);
                mma8(acc[nt], a0, a1, a2, a3, b0, b1);
            }
        }
        __syncthreads();
    }

    const int r0 = m0 + wm * 16 + (lane >> 2);
    #pragma unroll
    for (int nt = 0; nt < 16; nt++) {
        int col = n0 + wn * 128 + nt * 8 + 2 * (lane & 3);
        float b0 = bias[col], b1 = bias[col + 1];
        if (r0 < M)
            *(float2*)(out + (size_t)r0 * 1024 + col) =
                make_float2(acc[nt][0] + b0, acc[nt][1] + b1);
        if (r0 + 8 < M)
            *(float2*)(out + (size_t)(r0 + 8) * 1024 + col) =
                make_float2(acc[nt][2] + b0, acc[nt][3] + b1);
    }
}

// =================== k3: relu(pooled+b1) @ Wt1 + bt1 (32 rows/block) ===================
__global__ void __launch_bounds__(512)
k3_neigh_out(const float* __restrict__ b1, const float* __restrict__ Wt1,
             const float* __restrict__ bt1, float* __restrict__ out, int B)
{
    __shared__ float ps[320];
    const int o = threadIdx.x;
    const int b0 = blockIdx.x * 32;
    const int nrows = min(32, B - b0);

    for (int idx = o; idx < nrows * 10; idx += 512)
        ps[idx] = fmaxf(g_pooled[(size_t)b0 * 10 + idx] + b1[idx % 10], 0.0f);
    ull wtp[5];
    #pragma unroll
    for (int jp = 0; jp < 5; jp++)
        wtp[jp] = pk2(Wt1[(2 * jp) * 512 + o], Wt1[(2 * jp + 1) * 512 + o]);
    float bias = bt1[o];
    __syncthreads();

    #pragma unroll 1
    for (int r = 0; r < nrows; r++) {
        const ull* pr = (const ull*)&ps[r * 10];
        ull s2 = 0ull;
        #pragma unroll
        for (int jp = 0; jp < 5; jp++) fma2(s2, pr[jp], wtp[jp]);
        float2 t = upk2(s2);
        out[(size_t)(b0 + r) * 1024 + 512 + o] = t.x + t.y + bias;
    }
}

// ---------------------------------------------------------------------------
typedef CUresult (*EncodeFn)(CUtensorMap*, CUtensorMapDataType, cuuint32_t, void*,
                             const cuuint64_t*, const cuuint64_t*, const cuuint32_t*,
                             const cuuint32_t*, CUtensorMapInterleave, CUtensorMapSwizzle,
                             CUtensorMapL2promotion, CUtensorMapFloatOOBfill);

extern "C" void kernel_launch(void* const* d_in, const int* in_sizes, int n_in,
                              void* d_out, int out_size)
{
    const float* self_vecs = (const float*)d_in[0];
    const float* neigh     = (const float*)d_in[1];
    const float* W1        = (const float*)d_in[2];
    const float* b1        = (const float*)d_in[3];
    const float* Wt1       = (const float*)d_in[4];
    const float* bt1       = (const float*)d_in[5];
    const float* Wt2       = (const float*)d_in[6];
    const float* bt2       = (const float*)d_in[7];
    float* out = (float*)d_out;

    const int B = in_sizes[0] / 256;

    EncodeFn enc = nullptr;
    cudaDriverEntryPointQueryResult qr;
    cudaGetDriverEntryPointByVersion("cuTensorMapEncodeTiled", (void**)&enc, 12000,
                                     cudaEnableDefault, &qr);
    CUtensorMap tN;
    {
        cuuint64_t gd[2] = {256ull, (cuuint64_t)B * 32ull};
        cuuint64_t gs[1] = {1024ull};
        cuuint32_t bx[2] = {32u, 256u}, es[2] = {1u, 1u};
        enc(&tN, CU_TENSOR_MAP_DATA_TYPE_FLOAT32, 2, (void*)neigh, gd, gs, bx, es,
            CU_TENSOR_MAP_INTERLEAVE_NONE, CU_TENSOR_MAP_SWIZZLE_128B,
            CU_TENSOR_MAP_L2_PROMOTION_L2_128B, CU_TENSOR_MAP_FLOAT_OOB_FILL_NONE);
    }

    cudaFuncSetAttribute(k1_neigh_pool, cudaFuncAttributeMaxDynamicSharedMemorySize, K1SMEM);
    k1_neigh_pool<<<148, 256, K1SMEM>>>(tN, W1, B);

    cudaFuncSetAttribute(k2_mma, cudaFuncAttributeMaxDynamicSharedMemorySize, K2SMEM);
    const int mtiles = (B + 127) / 128;
    k2_mma<<<mtiles * 2, 512, K2SMEM>>>(self_vecs, Wt2, bt2, out, B);

    k3_neigh_out<<<(B + 31) / 32, 512>>>(b1, Wt1, bt1, out, B);
}

// round 8
// speedup vs baseline: 1.3542x; 1.0237x over previous
#include <cuda_runtime.h>
#include <cuda.h>
#include <cstdint>

typedef unsigned long long ull;
#define FULLMASK 0xffffffffu

__device__ float g_pooled[20000 * 10];

__device__ __forceinline__ ull pk2(float x, float y) {
    ull r; asm("mov.b64 %0, {%1, %2};" : "=l"(r) : "f"(x), "f"(y)); return r;
}
__device__ __forceinline__ float2 upk2(ull p) {
    float2 t; asm("mov.b64 {%0, %1}, %2;" : "=f"(t.x), "=f"(t.y) : "l"(p)); return t;
}
__device__ __forceinline__ void fma2(ull& d, ull a, ull b) {
    asm("fma.rn.f32x2 %0, %1, %2, %0;" : "+l"(d) : "l"(a), "l"(b));
}
__device__ __forceinline__ void add2(ull& d, ull a) {
    asm("add.rn.f32x2 %0, %0, %1;" : "+l"(d) : "l"(a));
}
__device__ __forceinline__ float tf32r(float x) {
    uint32_t o; asm("cvt.rna.tf32.f32 %0, %1;" : "=r"(o) : "f"(x));
    return __uint_as_float(o);
}
__device__ __forceinline__ void mbar_wait(uint32_t mb, uint32_t ph) {
    uint32_t done;
    asm volatile("{\n\t.reg .pred p;\n\t"
        "mbarrier.try_wait.parity.acquire.cta.shared::cta.b64 p, [%1], %2;\n\t"
        "selp.b32 %0, 1, 0, p;\n\t}" : "=r"(done) : "r"(mb), "r"(ph) : "memory");
    while (!done) {
        asm volatile("{\n\t.reg .pred p;\n\t"
            "mbarrier.try_wait.parity.acquire.cta.shared::cta.b64 p, [%1], %2, 10000000;\n\t"
            "selp.b32 %0, 1, 0, p;\n\t}" : "=r"(done) : "r"(mb), "r"(ph) : "memory");
    }
}

// =================== k1 v3: TMA MLP+maxpool, warp-decoupled pipeline ===================
#define BUFB   32768
#define W1OFF  (4 * BUFB)            // 131072, W1 padded [256][16] = 16384 B
#define SCROFF (W1OFF + 16384)       // 147456, scratch 30720 B
#define MBOFF  (SCROFF + 30720)      // 178176: full[4] @ +0, empty[4] @ +32
#define K1SMEM (MBOFF + 64)

__global__ void __launch_bounds__(256, 1)
k1_neigh_pool(const __grid_constant__ CUtensorMap tmap,
              const float* __restrict__ W1, int B)
{
    extern __shared__ char sm[];
    float* w1s = (float*)(sm + W1OFF);
    ull* scr = (ull*)(sm + SCROFF);
    const uint32_t smb = (uint32_t)__cvta_generic_to_shared(sm);
    const uint32_t mbF = smb + MBOFF;
    const uint32_t mbE = smb + MBOFF + 32;
    const int t = threadIdx.x;
    const int lane = t & 31, warp = t >> 5;
    const int ds = t >> 6, rbase = t & 63;
    const int G = gridDim.x, bid = blockIdx.x;

    for (int i = t; i < 2560; i += 256) w1s[(i / 10) * 16 + (i % 10)] = W1[i];
    if (t == 0) {
        #pragma unroll
        for (int s = 0; s < 4; s++) {
            asm volatile("mbarrier.init.shared.b64 [%0], 1;" :: "r"(mbF + 8 * s) : "memory");
            asm volatile("mbarrier.init.shared.b64 [%0], 8;" :: "r"(mbE + 8 * s) : "memory");
        }
        asm volatile("fence.proxy.async.shared::cta;" ::: "memory");
    }
    __syncthreads();

    const int NT = (B * 32 + 255) >> 8;
    const int ntiles = (bid < NT) ? (NT - bid + G - 1) / G : 0;
    const int totc = ntiles * 8;

    auto issue = [&](int i) {
        if (i >= 4) mbar_wait(mbE + 8 * (i & 3), (uint32_t)(((i >> 2) - 1) & 1));
        int gt = bid + G * (i >> 3);
        uint32_t dst = smb + (i & 3) * BUFB;
        uint32_t mb = mbF + 8 * (i & 3);
        asm volatile("mbarrier.arrive.expect_tx.shared.b64 _, [%0], %1;"
                     :: "r"(mb), "r"(32768u) : "memory");
        int x = (i & 7) * 32, y = gt * 256;
        asm volatile("cp.async.bulk.tensor.2d.shared::cta.global.tile.mbarrier::complete_tx::bytes"
                     " [%0], [%1, {%2, %3}], [%4];"
                     :: "r"(dst), "l"(&tmap), "r"(x), "r"(y), "r"(mb) : "memory");
    };
    if (t == 0) { int pre = totc < 3 ? totc : 3; for (int i = 0; i < pre; i++) issue(i); }

    ull acc[4][5];
    #pragma unroll
    for (int q = 0; q < 4; q++)
        #pragma unroll
        for (int jp = 0; jp < 5; jp++) acc[q][jp] = 0ull;

    #pragma unroll 1
    for (int i = 0; i < totc; i++) {
        if (t == 0 && i + 3 < totc) issue(i + 3);
        mbar_wait(mbF + 8 * (i & 3), (uint32_t)((i >> 2) & 1));

        const char* bb = sm + (i & 3) * BUFB;
        const int c = i & 7;
        #pragma unroll
        for (int g = 0; g < 2; g++) {
            const int dg = c * 32 + ds * 8 + g * 4;
            ull wpk[4][5];
            #pragma unroll
            for (int dd = 0; dd < 4; dd++) {
                const float* wr = &w1s[(dg + dd) * 16];
                float4 wa = *(const float4*)wr;
                float4 wb = *(const float4*)(wr + 4);
                float2 wc = *(const float2*)(wr + 8);
                wpk[dd][0] = pk2(wa.x, wa.y);
                wpk[dd][1] = pk2(wa.z, wa.w);
                wpk[dd][2] = pk2(wb.x, wb.y);
                wpk[dd][3] = pk2(wb.z, wb.w);
                wpk[dd][4] = pk2(wc.x, wc.y);
            }
            #pragma unroll
            for (int q = 0; q < 4; q++) {
                int r = rbase + 64 * q;
                int off = r * 128 + (2 * ds + g) * 16;
                int phys = off ^ ((r & 7) << 4);
                float4 x = *(const float4*)(bb + phys);
                ull p0 = pk2(x.x, x.x), p1 = pk2(x.y, x.y);
                ull p2 = pk2(x.z, x.z), p3 = pk2(x.w, x.w);
                #pragma unroll
                for (int jp = 0; jp < 5; jp++) {
                    fma2(acc[q][jp], p0, wpk[0][jp]);
                    fma2(acc[q][jp], p1, wpk[1][jp]);
                    fma2(acc[q][jp], p2, wpk[2][jp]);
                    fma2(acc[q][jp], p3, wpk[3][jp]);
                }
            }
        }

        // done reading buffer (i & 3): one arrive per warp
        __syncwarp();
        if (lane == 0)
            asm volatile("mbarrier.arrive.shared.b64 _, [%0];"
                         :: "r"(mbE + 8 * (i & 3)) : "memory");

        if (c == 7) {
            const int gt = bid + G * (i >> 3);
            if (ds) {
                ull* dp = scr + (((ds - 1) * 64 + rbase) * 4) * 5;
                #pragma unroll
                for (int q = 0; q < 4; q++)
                    #pragma unroll
                    for (int jp = 0; jp < 5; jp++) dp[q * 5 + jp] = acc[q][jp];
            }
            __syncthreads();
            if (ds == 0) {
                #pragma unroll
                for (int s = 0; s < 3; s++) {
                    const ull* sp = scr + ((s * 64 + rbase) * 4) * 5;
                    #pragma unroll
                    for (int q = 0; q < 4; q++)
                        #pragma unroll
                        for (int jp = 0; jp < 5; jp++) add2(acc[q][jp], sp[q * 5 + jp]);
                }
                #pragma unroll
                for (int q = 0; q < 4; q++) {
                    float h[10];
                    #pragma unroll
                    for (int jp = 0; jp < 5; jp++) {
                        float2 v = upk2(acc[q][jp]);
                        h[2 * jp] = v.x; h[2 * jp + 1] = v.y;
                    }
                    #pragma unroll
                    for (int j = 0; j < 10; j++)
                        #pragma unroll
                        for (int o = 16; o > 0; o >>= 1)
                            h[j] = fmaxf(h[j], __shfl_xor_sync(FULLMASK, h[j], o));
                    if (lane == 0) {
                        int b = gt * 8 + 2 * q + warp;
                        if (b < B) {
                            #pragma unroll
                            for (int j = 0; j < 10; j++)
                                g_pooled[(size_t)b * 10 + j] = h[j];
                        }
                    }
                }
            }
            #pragma unroll
            for (int q = 0; q < 4; q++)
                #pragma unroll
                for (int jp = 0; jp < 5; jp++) acc[q][jp] = 0ull;
            __syncthreads();   // protect scratch reuse across tiles
        }
    }
}

// =================== k2: mma.sync tf32 GEMM, persistent grid ===================
#define APAD 36
#define BPAD 264
#define ABUF (128 * APAD)
#define BBUF (32 * BPAD)
#define K2SMEM ((2 * ABUF + 2 * BBUF) * 4)

__device__ __forceinline__ void mma8(float* c, uint32_t a0, uint32_t a1, uint32_t a2,
                                     uint32_t a3, uint32_t b0, uint32_t b1) {
    asm volatile("mma.sync.aligned.m16n8k8.row.col.f32.tf32.tf32.f32 "
                 "{%0,%1,%2,%3}, {%4,%5,%6,%7}, {%8,%9}, {%0,%1,%2,%3};"
                 : "+f"(c[0]), "+f"(c[1]), "+f"(c[2]), "+f"(c[3])
                 : "r"(a0), "r"(a1), "r"(a2), "r"(a3), "r"(b0), "r"(b1));
}

__global__ void __launch_bounds__(512, 1)
k2_mma(const float* __restrict__ A, const float* __restrict__ Bw,
       const float* __restrict__ bias, float* __restrict__ out, int M)
{
    extern __shared__ float sms[];
    float* As = sms;
    float* Bs = sms + 2 * ABUF;
    const int t = threadIdx.x;
    const int wid = t >> 5, lane = t & 31;
    const int wm = wid >> 1, wn = wid & 1;
    const int G = gridDim.x;
    const int jobs = ((M + 127) >> 7) * 2;

    auto load = [&](int m0, int n0, int kc, int buf) {
        float* as = As + buf * ABUF;
        float* bs = Bs + buf * BBUF;
        const int k0 = kc * 32;
        #pragma unroll
        for (int i = 0; i < 2; i++) {
            int idx = t + 512 * i;
            int row = idx >> 3, kq = (idx & 7) << 2;
            float4 v = make_float4(0.f, 0.f, 0.f, 0.f);
            if (m0 + row < M) v = *(const float4*)(A + (size_t)(m0 + row) * 256 + k0 + kq);
            float* d = &as[row * APAD + kq];
            d[0] = tf32r(v.x); d[1] = tf32r(v.y); d[2] = tf32r(v.z); d[3] = tf32r(v.w);
        }
        #pragma unroll
        for (int i = 0; i < 4; i++) {
            int idx = t + 512 * i;
            int k = idx >> 6, nq = (idx & 63) << 2;
            float4 v = *(const float4*)(Bw + (size_t)(k0 + k) * 512 + n0 + nq);
            float* d = &bs[k * BPAD + nq];
            d[0] = tf32r(v.x); d[1] = tf32r(v.y); d[2] = tf32r(v.z); d[3] = tf32r(v.w);
        }
    };

    #pragma unroll 1
    for (int j = blockIdx.x; j < jobs; j += G) {
        const int m0 = (j >> 1) * 128;
        const int n0 = (j & 1) * 256;

        float acc[16][4];
        #pragma unroll
        for (int nt = 0; nt < 16; nt++)
            #pragma unroll
            for (int jj = 0; jj < 4; jj++) acc[nt][jj] = 0.f;

        load(m0, n0, 0, 0);
        __syncthreads();

        #pragma unroll 1
        for (int kc = 0; kc < 8; kc++) {
            if (kc + 1 < 8) load(m0, n0, kc + 1, (kc + 1) & 1);
            const float* as = As + (kc & 1) * ABUF;
            const float* bs = Bs + (kc & 1) * BBUF;
            const int r0 = wm * 16 + (lane >> 2);
            #pragma unroll
            for (int s = 0; s < 4; s++) {
                const int c0 = s * 8 + (lane & 3);
                uint32_t a0 = __float_as_uint(as[r0 * APAD + c0]);
                uint32_t a1 = __float_as_uint(as[(r0 + 8) * APAD + c0]);
                uint32_t a2 = __float_as_uint(as[r0 * APAD + c0 + 4]);
                uint32_t a3 = __float_as_uint(as[(r0 + 8) * APAD + c0 + 4]);
                const int kb0 = (s * 8 + (lane & 3)) * BPAD;
                const int kb1 = kb0 + 4 * BPAD;
                const int nb = wn * 128 + (lane >> 2);
                #pragma unroll
                for (int nt = 0; nt < 16; nt++) {
                    uint32_t b0 = __float_as_uint(bs[kb0 + nb + nt * 8]);
                    uint32_t b1 = __float_as_uint(bs[kb1 + nb + nt * 8]);
                    mma8(acc[nt], a0, a1, a2, a3, b0, b1);
                }
            }
            __syncthreads();
        }

        const int r0 = m0 + wm * 16 + (lane >> 2);
        #pragma unroll
        for (int nt = 0; nt < 16; nt++) {
            int col = n0 + wn * 128 + nt * 8 + 2 * (lane & 3);
            float b0 = bias[col], b1 = bias[col + 1];
            if (r0 < M)
                *(float2*)(out + (size_t)r0 * 1024 + col) =
                    make_float2(acc[nt][0] + b0, acc[nt][1] + b1);
            if (r0 + 8 < M)
                *(float2*)(out + (size_t)(r0 + 8) * 1024 + col) =
                    make_float2(acc[nt][2] + b0, acc[nt][3] + b1);
        }
    }
}

// =================== k3: relu(pooled+b1) @ Wt1 + bt1 ===================
__global__ void __launch_bounds__(512)
k3_neigh_out(const float* __restrict__ b1, const float* __restrict__ Wt1,
             const float* __restrict__ bt1, float* __restrict__ out, int B)
{
    __shared__ float ps[320];
    const int o = threadIdx.x;
    const int b0 = blockIdx.x * 32;
    const int nrows = min(32, B - b0);

    for (int idx = o; idx < nrows * 10; idx += 512)
        ps[idx] = fmaxf(g_pooled[(size_t)b0 * 10 + idx] + b1[idx % 10], 0.0f);
    ull wtp[5];
    #pragma unroll
    for (int jp = 0; jp < 5; jp++)
        wtp[jp] = pk2(Wt1[(2 * jp) * 512 + o], Wt1[(2 * jp + 1) * 512 + o]);
    float bias = bt1[o];
    __syncthreads();

    #pragma unroll 1
    for (int r = 0; r < nrows; r++) {
        const ull* pr = (const ull*)&ps[r * 10];
        ull s2 = 0ull;
        #pragma unroll
        for (int jp = 0; jp < 5; jp++) fma2(s2, pr[jp], wtp[jp]);
        float2 t = upk2(s2);
        out[(size_t)(b0 + r) * 1024 + 512 + o] = t.x + t.y + bias;
    }
}

// ---------------------------------------------------------------------------
typedef CUresult (*EncodeFn)(CUtensorMap*, CUtensorMapDataType, cuuint32_t, void*,
                             const cuuint64_t*, const cuuint64_t*, const cuuint32_t*,
                             const cuuint32_t*, CUtensorMapInterleave, CUtensorMapSwizzle,
                             CUtensorMapL2promotion, CUtensorMapFloatOOBfill);

extern "C" void kernel_launch(void* const* d_in, const int* in_sizes, int n_in,
                              void* d_out, int out_size)
{
    const float* self_vecs = (const float*)d_in[0];
    const float* neigh     = (const float*)d_in[1];
    const float* W1        = (const float*)d_in[2];
    const float* b1        = (const float*)d_in[3];
    const float* Wt1       = (const float*)d_in[4];
    const float* bt1       = (const float*)d_in[5];
    const float* Wt2       = (const float*)d_in[6];
    const float* bt2       = (const float*)d_in[7];
    float* out = (float*)d_out;

    const int B = in_sizes[0] / 256;

    EncodeFn enc = nullptr;
    cudaDriverEntryPointQueryResult qr;
    cudaGetDriverEntryPointByVersion("cuTensorMapEncodeTiled", (void**)&enc, 12000,
                                     cudaEnableDefault, &qr);
    CUtensorMap tN;
    {
        cuuint64_t gd[2] = {256ull, (cuuint64_t)B * 32ull};
        cuuint64_t gs[1] = {1024ull};
        cuuint32_t bx[2] = {32u, 256u}, es[2] = {1u, 1u};
        enc(&tN, CU_TENSOR_MAP_DATA_TYPE_FLOAT32, 2, (void*)neigh, gd, gs, bx, es,
            CU_TENSOR_MAP_INTERLEAVE_NONE, CU_TENSOR_MAP_SWIZZLE_128B,
            CU_TENSOR_MAP_L2_PROMOTION_L2_128B, CU_TENSOR_MAP_FLOAT_OOB_FILL_NONE);
    }

    cudaFuncSetAttribute(k1_neigh_pool, cudaFuncAttributeMaxDynamicSharedMemorySize, K1SMEM);
    k1_neigh_pool<<<148, 256, K1SMEM>>>(tN, W1, B);

    cudaFuncSetAttribute(k2_mma, cudaFuncAttributeMaxDynamicSharedMemorySize, K2SMEM);
    k2_mma<<<148, 512, K2SMEM>>>(self_vecs, Wt2, bt2, out, B);

    k3_neigh_out<<<(B + 31) / 32, 512>>>(b1, Wt1, bt1, out, B);
}

// round 9
// speedup vs baseline: 1.7142x; 1.2658x over previous
#include <cuda_runtime.h>
#include <cuda.h>
#include <cstdint>

typedef unsigned long long ull;
#define FULLMASK 0xffffffffu
#define BAR(id, n) asm volatile("bar.sync %0, %1;" :: "r"(id), "r"(n) : "memory")

__device__ float g_pooled[20000 * 10];

__device__ __forceinline__ ull pk2(float x, float y) {
    ull r; asm("mov.b64 %0, {%1, %2};" : "=l"(r) : "f"(x), "f"(y)); return r;
}
__device__ __forceinline__ float2 upk2(ull p) {
    float2 t; asm("mov.b64 {%0, %1}, %2;" : "=f"(t.x), "=f"(t.y) : "l"(p)); return t;
}
__device__ __forceinline__ void fma2(ull& d, ull a, ull b) {
    asm("fma.rn.f32x2 %0, %1, %2, %0;" : "+l"(d) : "l"(a), "l"(b));
}
__device__ __forceinline__ void add2(ull& d, ull a) {
    asm("add.rn.f32x2 %0, %0, %1;" : "+l"(d) : "l"(a));
}
__device__ __forceinline__ float tf32r(float x) {
    uint32_t o; asm("cvt.rna.tf32.f32 %0, %1;" : "=r"(o) : "f"(x));
    return __uint_as_float(o);
}
__device__ __forceinline__ void mbar_wait(uint32_t mb, uint32_t ph) {
    uint32_t done;
    asm volatile("{\n\t.reg .pred p;\n\t"
        "mbarrier.try_wait.parity.acquire.cta.shared::cta.b64 p, [%1], %2;\n\t"
        "selp.b32 %0, 1, 0, p;\n\t}" : "=r"(done) : "r"(mb), "r"(ph) : "memory");
    while (!done) {
        asm volatile("{\n\t.reg .pred p;\n\t"
            "mbarrier.try_wait.parity.acquire.cta.shared::cta.b64 p, [%1], %2, 10000000;\n\t"
            "selp.b32 %0, 1, 0, p;\n\t}" : "=r"(done) : "r"(mb), "r"(ph) : "memory");
    }
}
__device__ __forceinline__ void mma8(float* c, uint32_t a0, uint32_t a1, uint32_t a2,
                                     uint32_t a3, uint32_t b0, uint32_t b1) {
    asm volatile("mma.sync.aligned.m16n8k8.row.col.f32.tf32.tf32.f32 "
                 "{%0,%1,%2,%3}, {%4,%5,%6,%7}, {%8,%9}, {%0,%1,%2,%3};"
                 : "+f"(c[0]), "+f"(c[1]), "+f"(c[2]), "+f"(c[3])
                 : "r"(a0), "r"(a1), "r"(a2), "r"(a3), "r"(b0), "r"(b1));
}

// ---- smem layout (bytes) ----
#define BUFB   32768
#define W1OFF  (4 * BUFB)            // 131072, W1 [256][16]
#define SCROFF (W1OFF + 16384)       // 147456
#define MBOFF  (SCROFF + 30720)      // 178176: full[4], empty[4]
#define K2AOFF (MBOFF + 64)          // 178240: A [64][20] = 5120 B
#define K2BOFF (K2AOFF + 5120)       // 183360: B [16][136] = 8704 B
#define SMEMT  (K2BOFF + 8704)       // 192064

__global__ void __launch_bounds__(384, 1)
fused_k1k2(const __grid_constant__ CUtensorMap tmap,
           const float* __restrict__ W1,
           const float* __restrict__ A, const float* __restrict__ Bw,
           const float* __restrict__ bt2, float* __restrict__ out, int B)
{
    extern __shared__ char sm[];
    const uint32_t smb = (uint32_t)__cvta_generic_to_shared(sm);
    const int t = threadIdx.x;
    const int G = gridDim.x, bid = blockIdx.x;

    if (t < 256) {
        // ================= k1: TMA neighbor MLP + maxpool (proven) =================
        float* w1s = (float*)(sm + W1OFF);
        ull* scr = (ull*)(sm + SCROFF);
        const uint32_t mbF = smb + MBOFF;
        const uint32_t mbE = smb + MBOFF + 32;
        const int lane = t & 31, warp = t >> 5;
        const int ds = t >> 6, rbase = t & 63;

        for (int i = t; i < 2560; i += 256) w1s[(i / 10) * 16 + (i % 10)] = W1[i];
        if (t == 0) {
            #pragma unroll
            for (int s = 0; s < 4; s++) {
                asm volatile("mbarrier.init.shared.b64 [%0], 1;" :: "r"(mbF + 8 * s) : "memory");
                asm volatile("mbarrier.init.shared.b64 [%0], 8;" :: "r"(mbE + 8 * s) : "memory");
            }
            asm volatile("fence.proxy.async.shared::cta;" ::: "memory");
        }
        BAR(1, 256);

        const int NT = (B * 32 + 255) >> 8;
        const int ntiles = (bid < NT) ? (NT - bid + G - 1) / G : 0;
        const int totc = ntiles * 8;

        auto issue = [&](int i) {
            if (i >= 4) mbar_wait(mbE + 8 * (i & 3), (uint32_t)(((i >> 2) - 1) & 1));
            int gt = bid + G * (i >> 3);
            uint32_t dst = smb + (i & 3) * BUFB;
            uint32_t mb = mbF + 8 * (i & 3);
            asm volatile("mbarrier.arrive.expect_tx.shared.b64 _, [%0], %1;"
                         :: "r"(mb), "r"(32768u) : "memory");
            int x = (i & 7) * 32, y = gt * 256;
            asm volatile("cp.async.bulk.tensor.2d.shared::cta.global.tile.mbarrier::complete_tx::bytes"
                         " [%0], [%1, {%2, %3}], [%4];"
                         :: "r"(dst), "l"(&tmap), "r"(x), "r"(y), "r"(mb) : "memory");
        };
        if (t == 0) { int pre = totc < 3 ? totc : 3; for (int i = 0; i < pre; i++) issue(i); }

        ull acc[4][5];
        #pragma unroll
        for (int q = 0; q < 4; q++)
            #pragma unroll
            for (int jp = 0; jp < 5; jp++) acc[q][jp] = 0ull;

        #pragma unroll 1
        for (int i = 0; i < totc; i++) {
            if (t == 0 && i + 3 < totc) issue(i + 3);
            mbar_wait(mbF + 8 * (i & 3), (uint32_t)((i >> 2) & 1));

            const char* bb = sm + (i & 3) * BUFB;
            const int c = i & 7;
            #pragma unroll
            for (int g = 0; g < 2; g++) {
                const int dg = c * 32 + ds * 8 + g * 4;
                ull wpk[4][5];
                #pragma unroll
                for (int dd = 0; dd < 4; dd++) {
                    const float* wr = &w1s[(dg + dd) * 16];
                    float4 wa = *(const float4*)wr;
                    float4 wb = *(const float4*)(wr + 4);
                    float2 wc = *(const float2*)(wr + 8);
                    wpk[dd][0] = pk2(wa.x, wa.y);
                    wpk[dd][1] = pk2(wa.z, wa.w);
                    wpk[dd][2] = pk2(wb.x, wb.y);
                    wpk[dd][3] = pk2(wb.z, wb.w);
                    wpk[dd][4] = pk2(wc.x, wc.y);
                }
                #pragma unroll
                for (int q = 0; q < 4; q++) {
                    int r = rbase + 64 * q;
                    int off = r * 128 + (2 * ds + g) * 16;
                    int phys = off ^ ((r & 7) << 4);
                    float4 x = *(const float4*)(bb + phys);
                    ull p0 = pk2(x.x, x.x), p1 = pk2(x.y, x.y);
                    ull p2 = pk2(x.z, x.z), p3 = pk2(x.w, x.w);
                    #pragma unroll
                    for (int jp = 0; jp < 5; jp++) {
                        fma2(acc[q][jp], p0, wpk[0][jp]);
                        fma2(acc[q][jp], p1, wpk[1][jp]);
                        fma2(acc[q][jp], p2, wpk[2][jp]);
                        fma2(acc[q][jp], p3, wpk[3][jp]);
                    }
                }
            }

            __syncwarp();
            if (lane == 0)
                asm volatile("mbarrier.arrive.shared.b64 _, [%0];"
                             :: "r"(mbE + 8 * (i & 3)) : "memory");

            if (c == 7) {
                const int gt = bid + G * (i >> 3);
                if (ds) {
                    ull* dp = scr + (((ds - 1) * 64 + rbase) * 4) * 5;
                    #pragma unroll
                    for (int q = 0; q < 4; q++)
                        #pragma unroll
                        for (int jp = 0; jp < 5; jp++) dp[q * 5 + jp] = acc[q][jp];
                }
                BAR(1, 256);
                if (ds == 0) {
                    #pragma unroll
                    for (int s = 0; s < 3; s++) {
                        const ull* sp = scr + ((s * 64 + rbase) * 4) * 5;
                        #pragma unroll
                        for (int q = 0; q < 4; q++)
                            #pragma unroll
                            for (int jp = 0; jp < 5; jp++) add2(acc[q][jp], sp[q * 5 + jp]);
                    }
                    #pragma unroll
                    for (int q = 0; q < 4; q++) {
                        float h[10];
                        #pragma unroll
                        for (int jp = 0; jp < 5; jp++) {
                            float2 v = upk2(acc[q][jp]);
                            h[2 * jp] = v.x; h[2 * jp + 1] = v.y;
                        }
                        #pragma unroll
                        for (int j = 0; j < 10; j++)
                            #pragma unroll
                            for (int o = 16; o > 0; o >>= 1)
                                h[j] = fmaxf(h[j], __shfl_xor_sync(FULLMASK, h[j], o));
                        if (lane == 0) {
                            int b = gt * 8 + 2 * q + warp;
                            if (b < B) {
                                #pragma unroll
                                for (int j = 0; j < 10; j++)
                                    g_pooled[(size_t)b * 10 + j] = h[j];
                            }
                        }
                    }
                }
                #pragma unroll
                for (int q = 0; q < 4; q++)
                    #pragma unroll
                    for (int jp = 0; jp < 5; jp++) acc[q][jp] = 0ull;
                BAR(1, 256);
            }
        }
    } else {
        // ================= k2: tf32 mma self @ Wt2 + bt2 =================
        float* as = (float*)(sm + K2AOFF);   // [64][20]
        float* bs = (float*)(sm + K2BOFF);   // [16][136]
        const int wt = t - 256;              // 0..127
        const int w = wt >> 5, lane = wt & 31;
        const int M = B;
        const int jobs = ((M + 63) >> 6) * 4;
        const int ar = lane >> 2, ak = lane & 3;

        float4 ra[2], rb[4];
        #pragma unroll 1
        for (int j = bid; j < jobs; j += G) {
            const int m0 = (j >> 2) * 64;
            const int n0 = (j & 3) * 128;

            float acc[4][4][4];
            #pragma unroll
            for (int mt = 0; mt < 4; mt++)
                #pragma unroll
                for (int nt = 0; nt < 4; nt++)
                    #pragma unroll
                    for (int e = 0; e < 4; e++) acc[mt][nt][e] = 0.f;

            // stage chunk 0 in regs
            #pragma unroll
            for (int i = 0; i < 2; i++) {
                int idx = wt + 128 * i, row = idx >> 2, kq = (idx & 3) << 2;
                ra[i] = make_float4(0.f, 0.f, 0.f, 0.f);
                if (m0 + row < M) ra[i] = *(const float4*)(A + (size_t)(m0 + row) * 256 + kq);
            }
            #pragma unroll
            for (int i = 0; i < 4; i++) {
                int idx = wt + 128 * i, k = idx >> 5, nq = (idx & 31) << 2;
                rb[i] = *(const float4*)(Bw + (size_t)k * 512 + n0 + nq);
            }

            #pragma unroll 1
            for (int kc = 0; kc < 16; kc++) {
                BAR(2, 128);   // previous compute done, smem reusable
                #pragma unroll
                for (int i = 0; i < 2; i++) {
                    int idx = wt + 128 * i, row = idx >> 2, kq = (idx & 3) << 2;
                    float* d = &as[row * 20 + kq];
                    d[0] = tf32r(ra[i].x); d[1] = tf32r(ra[i].y);
                    d[2] = tf32r(ra[i].z); d[3] = tf32r(ra[i].w);
                }
                #pragma unroll
                for (int i = 0; i < 4; i++) {
                    int idx = wt + 128 * i, k = idx >> 5, nq = (idx & 31) << 2;
                    float* d = &bs[k * 136 + nq];
                    d[0] = tf32r(rb[i].x); d[1] = tf32r(rb[i].y);
                    d[2] = tf32r(rb[i].z); d[3] = tf32r(rb[i].w);
                }
                if (kc + 1 < 16) {   // prefetch next chunk into regs (hides LDG)
                    int k0 = (kc + 1) * 16;
                    #pragma unroll
                    for (int i = 0; i < 2; i++) {
                        int idx = wt + 128 * i, row = idx >> 2, kq = (idx & 3) << 2;
                        ra[i] = make_float4(0.f, 0.f, 0.f, 0.f);
                        if (m0 + row < M)
                            ra[i] = *(const float4*)(A + (size_t)(m0 + row) * 256 + k0 + kq);
                    }
                    #pragma unroll
                    for (int i = 0; i < 4; i++) {
                        int idx = wt + 128 * i, k = idx >> 5, nq = (idx & 31) << 2;
                        rb[i] = *(const float4*)(Bw + (size_t)(k0 + k) * 512 + n0 + nq);
                    }
                }
                BAR(2, 128);   // smem tiles visible
                #pragma unroll
                for (int s = 0; s < 2; s++) {
                    uint32_t a[4][4];
                    #pragma unroll
                    for (int mt = 0; mt < 4; mt++) {
                        const float* ap = &as[(mt * 16 + ar) * 20 + s * 8 + ak];
                        a[mt][0] = __float_as_uint(ap[0]);
                        a[mt][1] = __float_as_uint(ap[8 * 20]);
                        a[mt][2] = __float_as_uint(ap[4]);
                        a[mt][3] = __float_as_uint(ap[8 * 20 + 4]);
                    }
                    #pragma unroll
                    for (int nt = 0; nt < 4; nt++) {
                        int nb = w * 32 + nt * 8 + ar;
                        uint32_t b0 = __float_as_uint(bs[(s * 8 + ak) * 136 + nb]);
                        uint32_t b1 = __float_as_uint(bs[(s * 8 + 4 + ak) * 136 + nb]);
                        #pragma unroll
                        for (int mt = 0; mt < 4; mt++)
                            mma8(acc[mt][nt], a[mt][0], a[mt][1], a[mt][2], a[mt][3], b0, b1);
                    }
                }
            }

            #pragma unroll
            for (int mt = 0; mt < 4; mt++) {
                int r0 = m0 + mt * 16 + ar;
                #pragma unroll
                for (int nt = 0; nt < 4; nt++) {
                    int col = n0 + w * 32 + nt * 8 + 2 * ak;
                    float bv0 = bt2[col], bv1 = bt2[col + 1];
                    if (r0 < M)
                        *(float2*)(out + (size_t)r0 * 1024 + col) =
                            make_float2(acc[mt][nt][0] + bv0, acc[mt][nt][1] + bv1);
                    if (r0 + 8 < M)
                        *(float2*)(out + (size_t)(r0 + 8) * 1024 + col) =
                            make_float2(acc[mt][nt][2] + bv0, acc[mt][nt][3] + bv1);
                }
            }
        }
    }
}

// =================== k3: relu(pooled+b1) @ Wt1 + bt1 ===================
__global__ void __launch_bounds__(512)
k3_neigh_out(const float* __restrict__ b1, const float* __restrict__ Wt1,
             const float* __restrict__ bt1, float* __restrict__ out, int B)
{
    __shared__ float ps[320];
    const int o = threadIdx.x;
    const int b0 = blockIdx.x * 32;
    const int nrows = min(32, B - b0);

    for (int idx = o; idx < nrows * 10; idx += 512)
        ps[idx] = fmaxf(g_pooled[(size_t)b0 * 10 + idx] + b1[idx % 10], 0.0f);
    ull wtp[5];
    #pragma unroll
    for (int jp = 0; jp < 5; jp++)
        wtp[jp] = pk2(Wt1[(2 * jp) * 512 + o], Wt1[(2 * jp + 1) * 512 + o]);
    float bias = bt1[o];
    __syncthreads();

    #pragma unroll 1
    for (int r = 0; r < nrows; r++) {
        const ull* pr = (const ull*)&ps[r * 10];
        ull s2 = 0ull;
        #pragma unroll
        for (int jp = 0; jp < 5; jp++) fma2(s2, pr[jp], wtp[jp]);
        float2 t = upk2(s2);
        out[(size_t)(b0 + r) * 1024 + 512 + o] = t.x + t.y + bias;
    }
}

// ---------------------------------------------------------------------------
typedef CUresult (*EncodeFn)(CUtensorMap*, CUtensorMapDataType, cuuint32_t, void*,
                             const cuuint64_t*, const cuuint64_t*, const cuuint32_t*,
                             const cuuint32_t*, CUtensorMapInterleave, CUtensorMapSwizzle,
                             CUtensorMapL2promotion, CUtensorMapFloatOOBfill);

extern "C" void kernel_launch(void* const* d_in, const int* in_sizes, int n_in,
                              void* d_out, int out_size)
{
    const float* self_vecs = (const float*)d_in[0];
    const float* neigh     = (const float*)d_in[1];
    const float* W1        = (const float*)d_in[2];
    const float* b1        = (const float*)d_in[3];
    const float* Wt1       = (const float*)d_in[4];
    const float* bt1       = (const float*)d_in[5];
    const float* Wt2       = (const float*)d_in[6];
    const float* bt2       = (const float*)d_in[7];
    float* out = (float*)d_out;

    const int B = in_sizes[0] / 256;

    EncodeFn enc = nullptr;
    cudaDriverEntryPointQueryResult qr;
    cudaGetDriverEntryPointByVersion("cuTensorMapEncodeTiled", (void**)&enc, 12000,
                                     cudaEnableDefault, &qr);
    CUtensorMap tN;
    {
        cuuint64_t gd[2] = {256ull, (cuuint64_t)B * 32ull};
        cuuint64_t gs[1] = {1024ull};
        cuuint32_t bx[2] = {32u, 256u}, es[2] = {1u, 1u};
        enc(&tN, CU_TENSOR_MAP_DATA_TYPE_FLOAT32, 2, (void*)neigh, gd, gs, bx, es,
            CU_TENSOR_MAP_INTERLEAVE_NONE, CU_TENSOR_MAP_SWIZZLE_128B,
            CU_TENSOR_MAP_L2_PROMOTION_L2_128B, CU_TENSOR_MAP_FLOAT_OOB_FILL_NONE);
    }

    cudaFuncSetAttribute(fused_k1k2, cudaFuncAttributeMaxDynamicSharedMemorySize, SMEMT);
    fused_k1k2<<<148, 384, SMEMT>>>(tN, W1, self_vecs, Wt2, bt2, out, B);

    k3_neigh_out<<<(B + 31) / 32, 512>>>(b1, Wt1, bt1, out, B);
}